// round 10
// baseline (speedup 1.0000x reference)
#include <cuda_runtime.h>
#include <cuda_bf16.h>

#define N_NODES 50000
#define N_EDGES 600000
#define DIM 128
#define LN_EPS 1e-5f

// ---------------- scratch (static device globals; no allocation) -------------
__device__ float4 g_agg4[N_NODES * (DIM / 4)];   // 25.6 MB aggregation buffer
__device__ float  g_deg_out[N_NODES];
__device__ float  g_deg_in[N_NODES];

// ---------------- f32x2 packed-FMA helpers (Blackwell) -----------------------
__device__ __forceinline__ void unpack2(unsigned long long v, float& a, float& b) {
    asm("mov.b64 {%0, %1}, %2;" : "=f"(a), "=f"(b) : "l"(v));
}
__device__ __forceinline__ void fma2(unsigned long long& d, unsigned long long a,
                                     unsigned long long b) {
    asm("fma.rn.f32x2 %0, %1, %2, %0;" : "+l"(d) : "l"(a), "l"(b));
}

// ---------------- K0: zero agg + degree counters ------------------------------
__global__ void zero_kernel(int nN) {
    int i = blockIdx.x * blockDim.x + threadIdx.x;
    int tot = nN * (DIM / 4);
    if (i < tot) g_agg4[i] = make_float4(0.f, 0.f, 0.f, 0.f);
    if (i < nN) { g_deg_out[i] = 0.f; g_deg_in[i] = 0.f; }
}

// ---------------- K1: degrees --------------------------------------------------
__global__ void degree_kernel(const int* __restrict__ src,
                              const int* __restrict__ dst, int nE) {
    int i = blockIdx.x * blockDim.x + threadIdx.x;
    if (i < nE) {
        atomicAdd(&g_deg_out[src[i]], 1.f);
        atomicAdd(&g_deg_in[dst[i]], 1.f);
    }
}

// ---------------- K2: edge scatter (warp per 2 edges, float4 atomics) ---------
__global__ void __launch_bounds__(256)
scatter_kernel(const float* __restrict__ feat,
               const int* __restrict__ src,
               const int* __restrict__ dst, int nE) {
    int gtid = blockIdx.x * blockDim.x + threadIdx.x;
    int w = gtid >> 5;
    int lane = gtid & 31;
    int e0 = w * 2;
    if (e0 >= nE) return;
    int e1 = e0 + 1;
    bool has1 = (e1 < nE);

    int s0 = __ldg(src + e0);
    int d0 = __ldg(dst + e0);
    int s1 = has1 ? __ldg(src + e1) : s0;
    int d1 = has1 ? __ldg(dst + e1) : d0;

    float ns0 = rsqrtf(fmaxf(__ldg(&g_deg_out[s0]), 1.f));
    float ns1 = rsqrtf(fmaxf(__ldg(&g_deg_out[s1]), 1.f));

    const float4* f4 = reinterpret_cast<const float4*>(feat);
    float4 v0 = __ldcg(f4 + (size_t)s0 * 32 + lane);
    float4 v1 = __ldcg(f4 + (size_t)s1 * 32 + lane);

    v0.x *= ns0; v0.y *= ns0; v0.z *= ns0; v0.w *= ns0;
    atomicAdd(&g_agg4[(size_t)d0 * 32 + lane], v0);
    if (has1) {
        v1.x *= ns1; v1.y *= ns1; v1.z *= ns1; v1.w *= ns1;
        atomicAdd(&g_agg4[(size_t)d1 * 32 + lane], v1);
    }
}

// ---------------- K3: fused GEMM + bias/scale + LN + ReLU ---------------------
// K-axis f32x2 packing: x pairs (k even, k odd) come free from the natural smem
// row layout (one LDS.128 = 2 packed pairs); W pre-packed in smem as
// w2[k2][c] = (W[2k2][c], W[2k2+1][c]). No pack MOVs in the mainloop.
// 640 threads = 20 warps x 4 nodes = 80 nodes/block; 625 blocks, no tail.
// Lane owns output cols {lane, lane+32, lane+64, lane+96}.
// smem: W-packed 128KB + x staging [80x256] 80KB = 208KB.
__global__ void __launch_bounds__(640, 1)
final_kernel(const float* __restrict__ feat,
             const float* __restrict__ fc_w, const float* __restrict__ fc_b,
             const float* __restrict__ res_w,
             const float* __restrict__ ln_g, const float* __restrict__ ln_b,
             float* __restrict__ out, int nN) {
    extern __shared__ float smem_f[];
    float2* wpk = reinterpret_cast<float2*>(smem_f);  // [128 k2][128 c] = 128 KB
    float*  xs  = smem_f + 32768;                      // 80*256 floats = 80 KB

    int tid = threadIdx.x;
    // --- pack W (fc_w rows k<128, res_w rows k>=128) into k-pair float2s ---
    for (int i = tid; i < 16384; i += 640) {
        int k2 = i >> 7, c = i & 127;
        int k0 = 2 * k2;
        float a0, a1;
        if (k0 < 128) {
            a0 = __ldg(fc_w + k0 * 128 + c);
            a1 = __ldg(fc_w + (k0 + 1) * 128 + c);
        } else {
            a0 = __ldg(res_w + (k0 - 128) * 128 + c);
            a1 = __ldg(res_w + (k0 - 127) * 128 + c);
        }
        wpk[i] = make_float2(a0, a1);
    }

    int lane = tid & 31;
    int warp = tid >> 5;
    int v0 = blockIdx.x * 80 + warp * 4;

    const float4* ga4 = g_agg4;
    const float4* ft4 = reinterpret_cast<const float4*>(feat);
    float* xw = xs + warp * 4 * 256;   // this warp's 4 node rows

    // --- stage x = [in_norm*agg(128) ; feat(128)] for 4 nodes ---
    float inrm[4];
#pragma unroll
    for (int n = 0; n < 4; n++) {
        int v = min(v0 + n, nN - 1);
        float t = rsqrtf(fmaxf(__ldg(&g_deg_in[v]), 1.f));
        inrm[n] = t;
        float4 a = __ldcg(ga4 + (size_t)v * 32 + lane);
        a.x *= t; a.y *= t; a.z *= t; a.w *= t;
        float* row = xw + n * 256;
        reinterpret_cast<float4*>(row)[lane]       = a;
        reinterpret_cast<float4*>(row + 128)[lane] = __ldg(ft4 + (size_t)v * 32 + lane);
    }
    __syncthreads();   // W pack + x staging both complete

    // --- mainloop: per k4 (4 k-values = 2 packed k-pairs) ---
    unsigned long long acc[4][4];
#pragma unroll
    for (int n = 0; n < 4; n++)
#pragma unroll
        for (int c = 0; c < 4; c++) acc[n][c] = 0ull;

    const unsigned long long* wp =
        reinterpret_cast<const unsigned long long*>(wpk);

#pragma unroll 2
    for (int k4 = 0; k4 < 64; k4++) {
        ulonglong2 xq[4];
#pragma unroll
        for (int n = 0; n < 4; n++)
            xq[n] = reinterpret_cast<const ulonglong2*>(xw + n * 256)[k4]; // bcast

        int ka = (2 * k4) * 128 + lane;
        unsigned long long wa[4], wb[4];
#pragma unroll
        for (int c = 0; c < 4; c++) {
            wa[c] = wp[ka + 32 * c];          // k-pair (4k4, 4k4+1)
            wb[c] = wp[ka + 128 + 32 * c];    // k-pair (4k4+2, 4k4+3)
        }
#pragma unroll
        for (int n = 0; n < 4; n++) {
#pragma unroll
            for (int c = 0; c < 4; c++) {
                fma2(acc[n][c], xq[n].x, wa[c]);
                fma2(acc[n][c], xq[n].y, wb[c]);
            }
        }
    }

    // --- epilogue: fold pairs, bias, LayerNorm, ReLU, store ---
    float bsc[4], gsc[4], bbs[4];
#pragma unroll
    for (int c = 0; c < 4; c++) {
        bsc[c] = __ldg(fc_b + lane + 32 * c);
        gsc[c] = __ldg(ln_g + lane + 32 * c);
        bbs[c] = __ldg(ln_b + lane + 32 * c);
    }

#pragma unroll
    for (int n = 0; n < 4; n++) {
        float y[4];
#pragma unroll
        for (int c = 0; c < 4; c++) {
            float lo, hi;
            unpack2(acc[n][c], lo, hi);
            y[c] = lo + hi + inrm[n] * bsc[c];
        }

        float s = y[0] + y[1] + y[2] + y[3];
#pragma unroll
        for (int o = 16; o > 0; o >>= 1) s += __shfl_xor_sync(0xffffffffu, s, o);
        float mu = s * (1.0f / 128.0f);

        float d[4];
        float ss = 0.f;
#pragma unroll
        for (int c = 0; c < 4; c++) { d[c] = y[c] - mu; ss += d[c] * d[c]; }
#pragma unroll
        for (int o = 16; o > 0; o >>= 1) ss += __shfl_xor_sync(0xffffffffu, ss, o);
        float rs = rsqrtf(ss * (1.0f / 128.0f) + LN_EPS);

        int v = v0 + n;
        if (v < nN) {
            float* orow = out + (size_t)v * DIM;
#pragma unroll
            for (int c = 0; c < 4; c++)
                orow[lane + 32 * c] = fmaxf(fmaf(d[c] * rs, gsc[c], bbs[c]), 0.f);
        }
    }
}

// ---------------- launcher -----------------------------------------------------
extern "C" void kernel_launch(void* const* d_in, const int* in_sizes, int n_in,
                              void* d_out, int out_size) {
    const float* feat  = (const float*)d_in[0];
    const int*   src   = (const int*)d_in[1];
    const int*   dst   = (const int*)d_in[2];
    const float* fc_w  = (const float*)d_in[3];
    const float* fc_b  = (const float*)d_in[4];
    const float* res_w = (const float*)d_in[5];
    const float* ln_g  = (const float*)d_in[6];
    const float* ln_b  = (const float*)d_in[7];
    float* out = (float*)d_out;

    int nN = in_sizes[0] / DIM;   // 50000
    int nE = in_sizes[1];         // 600000

    // K0: zero agg + degree counters
    {
        int tot = nN * (DIM / 4);
        zero_kernel<<<(tot + 255) / 256, 256>>>(nN);
    }
    // K1: degrees
    degree_kernel<<<(nE + 255) / 256, 256>>>(src, dst, nE);
    // K2: scatter-add of normalized source features (warp per 2 edges)
    {
        long long warps = ((long long)nE + 1) / 2;
        long long threads = warps * 32;
        int blocks = (int)((threads + 255) / 256);
        scatter_kernel<<<blocks, 256>>>(feat, src, dst, nE);
    }
    // K3: fused GEMM + bias + in_norm scale + residual + LN + ReLU
    {
        const int SMEM = (32768 + 20480) * 4;  // 208 KB
        cudaFuncSetAttribute(final_kernel,
                             cudaFuncAttributeMaxDynamicSharedMemorySize, SMEM);
        int blocks = (nN + 79) / 80;           // 625, exact
        final_kernel<<<blocks, 640, SMEM>>>(feat, fc_w, fc_b, res_w, ln_g, ln_b,
                                            out, nN);
    }
}